// round 13
// baseline (speedup 1.0000x reference)
#include <cuda_runtime.h>
#include <cuda_bf16.h>
#include <math.h>
#include <stdint.h>

#define Dm      128
#define BATCH   65536
#define NROWS   500000
#define TSLOTS  3

#define TILE_BYTES 32768           // 128 rows x 256B (128 bf16)
#define OFF_XHI  0
#define OFF_XLO  (1 * TILE_BYTES)
#define OFF_MHI  (2 * TILE_BYTES)
#define OFF_MLO  (3 * TILE_BYTES)
#define OFF_WHI  (4 * TILE_BYTES)
#define OFF_WLO  (5 * TILE_BYTES)
#define OFF_IDX  (6 * TILE_BYTES)
#define SMEM_REQ (6 * TILE_BYTES + 512)

#define WSET_BYTES (2 * TILE_BYTES)   // hi+lo image of one matrix

#define NTHREADS 512

__device__ int g_winner[NROWS];
// pre-converted, pre-swizzled bf16 hi/lo smem images of the 8 weight matrices
__device__ __align__(1024) char g_wt[8 * WSET_BYTES];

// ---------------- low-level helpers ----------------

__device__ __forceinline__ uint32_t smem_u32(const void* p) {
    uint32_t a;
    asm("{ .reg .u64 t; cvta.to.shared.u64 t, %1; cvt.u32.u64 %0, t; }" : "=r"(a) : "l"(p));
    return a;
}

// swizzled byte offset of 16B chunk kb (0..15) in row r (0..127)
__device__ __forceinline__ uint32_t toff(int r, int kb) {
    return (uint32_t)r * 256u + (uint32_t)(((kb ^ (r & 7)) & 15) << 4);
}

__device__ __forceinline__ void ldm4(unsigned* d, uint32_t a) {
    asm volatile("ldmatrix.sync.aligned.m8n8.x4.shared.b16 {%0,%1,%2,%3}, [%4];"
        : "=r"(d[0]), "=r"(d[1]), "=r"(d[2]), "=r"(d[3]) : "r"(a));
}

__device__ __forceinline__ void mma16816(float* d, const unsigned* a,
                                         unsigned b0, unsigned b1) {
    asm volatile("mma.sync.aligned.m16n8k16.row.col.f32.bf16.bf16.f32 "
        "{%0,%1,%2,%3}, {%4,%5,%6,%7}, {%8,%9}, {%0,%1,%2,%3};"
        : "+f"(d[0]), "+f"(d[1]), "+f"(d[2]), "+f"(d[3])
        : "r"(a[0]), "r"(a[1]), "r"(a[2]), "r"(a[3]), "r"(b0), "r"(b1));
}

__device__ __forceinline__ float sigf(float x) { return 1.0f / (1.0f + expf(-x)); }

// pack 8 fp32 -> 16B hi + 16B lo bf16 and store at (row, kb)
__device__ __forceinline__ void pack_store(char* smx, uint32_t offHi, uint32_t offLo,
                                           int row, int kb, const float* w8) {
    uint4 hi, lo;
    unsigned* hp = (unsigned*)&hi;
    unsigned* lp = (unsigned*)&lo;
#pragma unroll
    for (int q = 0; q < 4; q++) {
        float a = w8[2 * q], b = w8[2 * q + 1];
        __nv_bfloat16 ah = __float2bfloat16(a), bh = __float2bfloat16(b);
        __nv_bfloat16 al = __float2bfloat16(a - __bfloat162float(ah));
        __nv_bfloat16 bl = __float2bfloat16(b - __bfloat162float(bh));
        hp[q] = ((unsigned)__bfloat16_as_ushort(bh) << 16) | (unsigned)__bfloat16_as_ushort(ah);
        lp[q] = ((unsigned)__bfloat16_as_ushort(bl) << 16) | (unsigned)__bfloat16_as_ushort(al);
    }
    uint32_t a = toff(row, kb);
    *(uint4*)(smx + offHi + a) = hi;
    *(uint4*)(smx + offLo + a) = lo;
}

// stage 128x128 fp32 row-major matrix into hi/lo bf16 tiles — 256-thread version
__device__ __forceinline__ void stage_mat_256(const float* __restrict__ G, char* dst,
                                              uint32_t offHi, uint32_t offLo, int tid) {
    int row = tid >> 1, half = tid & 1;
    const float4* g4 = (const float4*)(G + (size_t)row * 128 + half * 64);
#pragma unroll
    for (int j = 0; j < 8; j++) {
        float4 qa = g4[2 * j], qb = g4[2 * j + 1];
        float w8[8] = { qa.x, qa.y, qa.z, qa.w, qb.x, qb.y, qb.z, qb.w };
        pack_store(dst, offHi, offLo, row, half * 8 + j, w8);
    }
}

// stage — 512-thread version (each thread: 32 consecutive floats of one row)
__device__ __forceinline__ void stage_mat_512(const float* __restrict__ G, char* dst,
                                              uint32_t offHi, uint32_t offLo, int tid) {
    int row = tid >> 2, q = tid & 3;
    const float4* g4 = (const float4*)(G + (size_t)row * 128 + q * 32);
#pragma unroll
    for (int j = 0; j < 4; j++) {
        float4 qa = g4[2 * j], qb = g4[2 * j + 1];
        float w8[8] = { qa.x, qa.y, qa.z, qa.w, qb.x, qb.y, qb.z, qb.w };
        pack_store(dst, offHi, offLo, row, q * 4 + j, w8);
    }
}

// cp.async the pre-built 64KB weight image for phase p into Ws (512 threads)
__device__ __forceinline__ void cp_w(uint32_t sb, int p, int tid) {
    uint32_t sdst = sb + OFF_WHI + (uint32_t)tid * 16u;
    const char* gsrc = g_wt + (size_t)p * WSET_BYTES + (size_t)tid * 16u;
#pragma unroll
    for (int i = 0; i < 8; i++) {
        asm volatile("cp.async.cg.shared.global [%0], [%1], 16;"
            :: "r"(sdst + (uint32_t)i * 8192u), "l"(gsrc + (size_t)i * 8192u));
    }
    asm volatile("cp.async.commit_group;" ::: "memory");
}
#define CP_WAIT() asm volatile("cp.async.wait_group 0;" ::: "memory")

// store fp32 pair (cols c, c+1; c even) of row r into hi/lo tiles
__device__ __forceinline__ void st_pair(char* smx, uint32_t offHi, uint32_t offLo,
                                        int r, int c, float v0, float v1) {
    uint32_t a = toff(r, c >> 3) + (uint32_t)(c & 7) * 2u;
    __nv_bfloat16 h0 = __float2bfloat16(v0), h1 = __float2bfloat16(v1);
    __nv_bfloat16 l0 = __float2bfloat16(v0 - __bfloat162float(h0));
    __nv_bfloat16 l1 = __float2bfloat16(v1 - __bfloat162float(h1));
    *(unsigned*)(smx + offHi + a) =
        ((unsigned)__bfloat16_as_ushort(h1) << 16) | (unsigned)__bfloat16_as_ushort(h0);
    *(unsigned*)(smx + offLo + a) =
        ((unsigned)__bfloat16_as_ushort(l1) << 16) | (unsigned)__bfloat16_as_ushort(l0);
}

// read fp32 pair (hi+lo) at (r, c)
__device__ __forceinline__ float2 ld_pair(const char* smx, uint32_t offHi, uint32_t offLo,
                                          int r, int c) {
    uint32_t a = toff(r, c >> 3) + (uint32_t)(c & 7) * 2u;
    unsigned h = *(const unsigned*)(smx + offHi + a);
    unsigned l = *(const unsigned*)(smx + offLo + a);
    float2 v;
    v.x = __bfloat162float(__ushort_as_bfloat16((unsigned short)(h & 0xffff))) +
          __bfloat162float(__ushort_as_bfloat16((unsigned short)(l & 0xffff)));
    v.y = __bfloat162float(__ushort_as_bfloat16((unsigned short)(h >> 16))) +
          __bfloat162float(__ushort_as_bfloat16((unsigned short)(l >> 16)));
    return v;
}

// FUSED single-pass bf16x3-split GEMM: acc += Ah·Wh + Ah·Wl + Al·Wh
// (each fragment loaded ONCE per k-step: 64 LDSM vs 96 in the 3-pass form)
__device__ __forceinline__ void gemm3(uint32_t sb, uint32_t offAhi, uint32_t offAlo,
                                      float acc[2][4][4], int m0, int n0, int lane) {
    const int rA  = m0 + (lane & 7) + ((lane >> 3) & 1) * 8;
    const int kA  = lane >> 4;            // A kb low bit
    const int rBb = (lane & 7) + (lane >> 4) * 8;
    const int kB  = (lane >> 3) & 1;      // B kb low bit
    const int swA = rA & 7;
    const uint32_t aH0 = sb + offAhi + (uint32_t)rA * 256u;
    const uint32_t aH1 = aH0 + 16u * 256u;
    const uint32_t aL0 = sb + offAlo + (uint32_t)rA * 256u;
    const uint32_t aL1 = aL0 + 16u * 256u;
#pragma unroll
    for (int s = 0; s < 8; s++) {
        int kb = 2 * s + kA;
        uint32_t ao = (uint32_t)((kb ^ swA) << 4);
        unsigned ah0[4], ah1[4], al0[4], al1[4];
        ldm4(ah0, aH0 + ao);
        ldm4(ah1, aH1 + ao);
        ldm4(al0, aL0 + ao);
        ldm4(al1, aL1 + ao);
        int kbB = 2 * s + kB;
#pragma unroll
        for (int q = 0; q < 2; q++) {
            int rB = n0 + q * 16 + rBb;
            uint32_t wo = (uint32_t)rB * 256u + (uint32_t)(((kbB ^ (rB & 7)) & 15) << 4);
            unsigned bh[4], bl[4];
            ldm4(bh, sb + OFF_WHI + wo);
            ldm4(bl, sb + OFF_WLO + wo);
            // Ah*Wh
            mma16816(acc[0][2 * q + 0], ah0, bh[0], bh[1]);
            mma16816(acc[0][2 * q + 1], ah0, bh[2], bh[3]);
            mma16816(acc[1][2 * q + 0], ah1, bh[0], bh[1]);
            mma16816(acc[1][2 * q + 1], ah1, bh[2], bh[3]);
            // Ah*Wl
            mma16816(acc[0][2 * q + 0], ah0, bl[0], bl[1]);
            mma16816(acc[0][2 * q + 1], ah0, bl[2], bl[3]);
            mma16816(acc[1][2 * q + 0], ah1, bl[0], bl[1]);
            mma16816(acc[1][2 * q + 1], ah1, bl[2], bl[3]);
            // Al*Wh
            mma16816(acc[0][2 * q + 0], al0, bh[0], bh[1]);
            mma16816(acc[0][2 * q + 1], al0, bh[2], bh[3]);
            mma16816(acc[1][2 * q + 0], al1, bh[0], bh[1]);
            mma16816(acc[1][2 * q + 1], al1, bh[2], bh[3]);
        }
    }
}

#define ZACC do {                                                         \
    _Pragma("unroll") for (int z1 = 0; z1 < 2; z1++)                      \
    _Pragma("unroll") for (int z2 = 0; z2 < 4; z2++)                      \
    _Pragma("unroll") for (int z3 = 0; z3 < 4; z3++) acc[z1][z2][z3] = 0.f; \
} while (0)

// ---------------- setup kernels ----------------

__global__ void k_winit() {
    int i = blockIdx.x * blockDim.x + threadIdx.x;
    if (i < NROWS) g_winner[i] = -1;
}
__global__ void k_wscatter(const int* __restrict__ idx) {
    int b = blockIdx.x * blockDim.x + threadIdx.x;
    if (b < BATCH) atomicMax(&g_winner[idx[b]], b);
}

// pre-convert the 8 weight matrices into swizzled bf16 hi/lo images
__global__ void k_wprep(const float* __restrict__ W1, const float* __restrict__ W2,
                        const float* __restrict__ W_ih, const float* __restrict__ W_hh) {
    const float* src;
    switch (blockIdx.x) {
        case 0: src = W1; break;
        case 1: src = W2; break;
        case 2: src = W_ih; break;                 // r, ih
        case 3: src = W_hh; break;                 // r, hh
        case 4: src = W_hh + 2 * 16384; break;     // n, hh
        case 5: src = W_ih + 2 * 16384; break;     // n, ih
        case 6: src = W_ih + 16384; break;         // z, ih
        default: src = W_hh + 16384; break;        // z, hh
    }
    char* dst = g_wt + (size_t)blockIdx.x * WSET_BYTES;
    stage_mat_256(src, dst, 0, TILE_BYTES, threadIdx.x);
}

// ---------------- tensor-core compute kernel (16 warps, fused split) ----------------

__global__ void __maxnreg__(128) k_compute(
    const float* __restrict__ x, const int* __restrict__ idx,
    const float* __restrict__ hist,
    const float* __restrict__ b1, const float* __restrict__ b2,
    const float* __restrict__ b_ih, const float* __restrict__ b_hh,
    float* __restrict__ out, float* __restrict__ memout,
    float* __restrict__ nh)
{
    extern __shared__ char smx[];
    const uint32_t sb = smem_u32(smx);
    int* sIdx = (int*)(smx + OFF_IDX);

    const int tid  = threadIdx.x;
    const int wid  = tid >> 5, lane = tid & 31;
    const int m0   = (wid & 3) * 32;
    const int n0   = (wid >> 2) * 32;
    const int rBase = lane >> 2;
    const int cBase = (lane & 3) * 2;
    const long long rowbase = (long long)blockIdx.x * 128;

    // prefetch W for P1 while we stage X and M
    cp_w(sb, 0, tid);

    // ---- stage X ----
    stage_mat_512(x + rowbase * Dm, smx, OFF_XHI, OFF_XLO, tid);

    // ---- gather + stage M (and write memout, cache idx) ----
    {
        int row = tid >> 2, q = tid & 3;
        int gi = idx[rowbase + row];
        if (q == 0) sIdx[row] = gi;
        const float4* g4 = (const float4*)(hist + (2LL * NROWS + gi) * Dm + q * 32);
        float4* mo = (float4*)(memout + (rowbase + row) * Dm + q * 32);
#pragma unroll
        for (int j = 0; j < 4; j++) {
            float4 qa = g4[2 * j], qb = g4[2 * j + 1];
            mo[2 * j] = qa; mo[2 * j + 1] = qb;
            float w8[8] = { qa.x, qa.y, qa.z, qa.w, qb.x, qb.y, qb.z, qb.w };
            pack_store(smx, OFF_MHI, OFF_MLO, row, q * 4 + j, w8);
        }
    }

    CP_WAIT();
    __syncthreads();

    float acc[2][4][4];
    float hold[2][4][4];

    // ===== P1: h1 = elu(x @ W1^T + b1) =====
    ZACC;
    gemm3(sb, OFF_XHI, OFF_XLO, acc, m0, n0, lane);
    __syncthreads();
    cp_w(sb, 1, tid);                               // W2, hidden under epilogue
#pragma unroll
    for (int nt = 0; nt < 4; nt++) {
        int c = n0 + nt * 8 + cBase;
        float2 bv = *(const float2*)(b1 + c);
#pragma unroll
        for (int mt = 0; mt < 2; mt++)
#pragma unroll
            for (int eh = 0; eh < 2; eh++) {
                int r = m0 + mt * 16 + rBase + eh * 8;
                float v0 = acc[mt][nt][eh * 2 + 0] + bv.x;
                float v1 = acc[mt][nt][eh * 2 + 1] + bv.y;
                v0 = (v0 > 0.f) ? v0 : expm1f(v0);
                v1 = (v1 > 0.f) ? v1 : expm1f(v1);
                st_pair(smx, OFF_XHI, OFF_XLO, r, c, v0, v1);
            }
    }
    CP_WAIT();
    __syncthreads();

    // ===== P2: xf = h1 @ W2^T + b2 =====
    ZACC;
    gemm3(sb, OFF_XHI, OFF_XLO, acc, m0, n0, lane);
    __syncthreads();
    cp_w(sb, 2, tid);                               // W_ih r
#pragma unroll
    for (int nt = 0; nt < 4; nt++) {
        int c = n0 + nt * 8 + cBase;
        float2 bv = *(const float2*)(b2 + c);
#pragma unroll
        for (int mt = 0; mt < 2; mt++)
#pragma unroll
            for (int eh = 0; eh < 2; eh++) {
                int r = m0 + mt * 16 + rBase + eh * 8;
                st_pair(smx, OFF_XHI, OFF_XLO, r, c,
                        acc[mt][nt][eh * 2 + 0] + bv.x,
                        acc[mt][nt][eh * 2 + 1] + bv.y);
            }
    }
    CP_WAIT();
    __syncthreads();

    // ===== P3: r = sigmoid(xf@Wihr^T + mem@Whhr^T + b_ihr + b_hhr) =====
    ZACC;
    gemm3(sb, OFF_XHI, OFF_XLO, acc, m0, n0, lane);
    __syncthreads();
    cp_w(sb, 3, tid);                               // W_hh r
    CP_WAIT();
    __syncthreads();
    gemm3(sb, OFF_MHI, OFF_MLO, acc, m0, n0, lane); // accumulate
    __syncthreads();
    cp_w(sb, 4, tid);                               // W_hh n
#pragma unroll
    for (int nt = 0; nt < 4; nt++) {
        int c = n0 + nt * 8 + cBase;
        float2 ba = *(const float2*)(b_ih + c);
        float2 bh = *(const float2*)(b_hh + c);
#pragma unroll
        for (int mt = 0; mt < 2; mt++)
#pragma unroll
            for (int e = 0; e < 4; e++) {
                float bb = (e & 1) ? (ba.y + bh.y) : (ba.x + bh.x);
                hold[mt][nt][e] = sigf(acc[mt][nt][e] + bb);
            }
    }
    CP_WAIT();
    __syncthreads();

    // ===== P4: hold = r * (mem@Whhn^T + b_hhn) =====
    ZACC;
    gemm3(sb, OFF_MHI, OFF_MLO, acc, m0, n0, lane);
    __syncthreads();
    cp_w(sb, 5, tid);                               // W_ih n
#pragma unroll
    for (int nt = 0; nt < 4; nt++) {
        int c = n0 + nt * 8 + cBase;
        float2 bv = *(const float2*)(b_hh + 256 + c);
#pragma unroll
        for (int mt = 0; mt < 2; mt++)
#pragma unroll
            for (int e = 0; e < 4; e++) {
                float bb = (e & 1) ? bv.y : bv.x;
                hold[mt][nt][e] *= (acc[mt][nt][e] + bb);
            }
    }
    CP_WAIT();
    __syncthreads();

    // ===== P5: hold = tanh(xf@Wihn^T + b_ihn + hold) =====
    ZACC;
    gemm3(sb, OFF_XHI, OFF_XLO, acc, m0, n0, lane);
    __syncthreads();
    cp_w(sb, 6, tid);                               // W_ih z
#pragma unroll
    for (int nt = 0; nt < 4; nt++) {
        int c = n0 + nt * 8 + cBase;
        float2 bv = *(const float2*)(b_ih + 256 + c);
#pragma unroll
        for (int mt = 0; mt < 2; mt++)
#pragma unroll
            for (int e = 0; e < 4; e++) {
                float bb = (e & 1) ? bv.y : bv.x;
                hold[mt][nt][e] = tanhf(acc[mt][nt][e] + bb + hold[mt][nt][e]);
            }
    }
    CP_WAIT();
    __syncthreads();

    // ===== P6: z gate + combine =====
    ZACC;
    gemm3(sb, OFF_XHI, OFF_XLO, acc, m0, n0, lane);
    __syncthreads();
    cp_w(sb, 7, tid);                               // W_hh z
    CP_WAIT();
    __syncthreads();
    gemm3(sb, OFF_MHI, OFF_MLO, acc, m0, n0, lane);
    // epilogue reads only M tiles (written before P1) — no sync needed
#pragma unroll
    for (int mt = 0; mt < 2; mt++)
#pragma unroll
        for (int eh = 0; eh < 2; eh++) {
            int r = m0 + mt * 16 + rBase + eh * 8;
            int grow = (int)rowbase + r;
            int gi = sIdx[r];
            bool win = (__ldg(&g_winner[gi]) == grow);
            float* orow = out + (long long)grow * Dm;
            float* hrow = nh + (2LL * NROWS + gi) * Dm;
#pragma unroll
            for (int nt = 0; nt < 4; nt++) {
                int c = n0 + nt * 8 + cBase;
                float2 ba = *(const float2*)(b_ih + 128 + c);
                float2 bh = *(const float2*)(b_hh + 128 + c);
                float2 mv = ld_pair(smx, OFF_MHI, OFF_MLO, r, c);
                float z0 = sigf(acc[mt][nt][eh * 2 + 0] + ba.x + bh.x);
                float z1 = sigf(acc[mt][nt][eh * 2 + 1] + ba.y + bh.y);
                float2 o;
                o.x = (1.f - z0) * hold[mt][nt][eh * 2 + 0] + z0 * mv.x;
                o.y = (1.f - z1) * hold[mt][nt][eh * 2 + 1] + z1 * mv.y;
                *(float2*)(orow + c) = o;
                if (win) *(float2*)(hrow + c) = o;
            }
        }
}

// ---------------- history copy (t=0,1 shift + t=2 non-winner) ----------------

__global__ void __maxnreg__(16) k_hist_copy(const float* __restrict__ hist,
                                            float* __restrict__ nh)
{
    const long long PER_T = (long long)NROWS * (Dm / 4);
    int t = blockIdx.y;
    long long rem = (long long)blockIdx.x * blockDim.x + threadIdx.x;
    int i = (int)(rem >> 5);
    int w = __ldg(&g_winner[i]);
    long long gid = (long long)t * PER_T + rem;
    if (t < TSLOTS - 1) {
        float4 v = __ldcs((const float4*)hist + gid + (w >= 0 ? PER_T : 0));
        __stcs((float4*)nh + gid, v);
    } else if (w < 0) {
        float4 v = __ldcs((const float4*)hist + gid);
        __stcs((float4*)nh + gid, v);
    }
}

// ---------------- launcher ----------------

extern "C" void kernel_launch(void* const* d_in, const int* in_sizes, int n_in,
                              void* d_out, int out_size) {
    (void)in_sizes; (void)n_in; (void)out_size;
    const float* x    = (const float*)d_in[0];
    const int*   idx  = (const int*)d_in[1];
    const float* hist = (const float*)d_in[2];
    const float* W1   = (const float*)d_in[3];
    const float* b1   = (const float*)d_in[4];
    const float* W2   = (const float*)d_in[5];
    const float* b2   = (const float*)d_in[6];
    const float* W_ih = (const float*)d_in[7];
    const float* b_ih = (const float*)d_in[8];
    const float* W_hh = (const float*)d_in[9];
    const float* b_hh = (const float*)d_in[10];

    float* out    = (float*)d_out;
    float* memout = out + (long long)BATCH * Dm;
    float* nh     = memout + (long long)BATCH * Dm;

    static cudaStream_t s2 = 0;
    static cudaEvent_t  eFork = 0, eJoin = 0;
    if (!s2) {
        cudaStreamCreateWithFlags(&s2, cudaStreamNonBlocking);
        cudaEventCreateWithFlags(&eFork, cudaEventDisableTiming);
        cudaEventCreateWithFlags(&eJoin, cudaEventDisableTiming);
        cudaFuncSetAttribute(k_compute, cudaFuncAttributeMaxDynamicSharedMemorySize,
                             SMEM_REQ);
    }

    k_winit<<<(NROWS + 511) / 512, 512>>>();
    k_wscatter<<<(BATCH + 255) / 256, 256>>>(idx);
    k_wprep<<<8, 256>>>(W1, W2, W_ih, W_hh);

    cudaEventRecord(eFork, 0);
    cudaStreamWaitEvent(s2, eFork, 0);

    k_compute<<<BATCH / 128, NTHREADS, SMEM_REQ>>>(x, idx, hist, b1, b2, b_ih, b_hh,
                                                   out, memout, nh);
    dim3 hg((unsigned)((long long)NROWS * (Dm / 4) / 128), TSLOTS);
    k_hist_copy<<<hg, 128, 0, s2>>>(hist, nh);

    cudaEventRecord(eJoin, s2);
    cudaStreamWaitEvent(0, eJoin, 0);
}

// round 14
// speedup vs baseline: 1.0007x; 1.0007x over previous
#include <cuda_runtime.h>
#include <cuda_bf16.h>
#include <math.h>
#include <stdint.h>

#define Dm      128
#define BATCH   65536
#define NROWS   500000
#define TSLOTS  3

#define TILE_BYTES 32768           // 128 rows x 256B (128 bf16)
#define OFF_XHI  0
#define OFF_XLO  (1 * TILE_BYTES)
#define OFF_MHI  (2 * TILE_BYTES)
#define OFF_MLO  (3 * TILE_BYTES)
#define OFF_WHI  (4 * TILE_BYTES)
#define OFF_WLO  (5 * TILE_BYTES)
#define OFF_IDX  (6 * TILE_BYTES)
#define SMEM_REQ (6 * TILE_BYTES + 512)

#define WSET_BYTES (2 * TILE_BYTES)   // hi+lo image of one matrix

#define NTHREADS 1024

__device__ int g_winner[NROWS];
// pre-converted, pre-swizzled bf16 hi/lo smem images of the 8 weight matrices
__device__ __align__(1024) char g_wt[8 * WSET_BYTES];

// ---------------- low-level helpers ----------------

__device__ __forceinline__ uint32_t smem_u32(const void* p) {
    uint32_t a;
    asm("{ .reg .u64 t; cvta.to.shared.u64 t, %1; cvt.u32.u64 %0, t; }" : "=r"(a) : "l"(p));
    return a;
}

// swizzled byte offset of 16B chunk kb (0..15) in row r (0..127)
__device__ __forceinline__ uint32_t toff(int r, int kb) {
    return (uint32_t)r * 256u + (uint32_t)(((kb ^ (r & 7)) & 15) << 4);
}

__device__ __forceinline__ void ldm4(unsigned* d, uint32_t a) {
    asm volatile("ldmatrix.sync.aligned.m8n8.x4.shared.b16 {%0,%1,%2,%3}, [%4];"
        : "=r"(d[0]), "=r"(d[1]), "=r"(d[2]), "=r"(d[3]) : "r"(a));
}

__device__ __forceinline__ void mma16816(float* d, const unsigned* a,
                                         unsigned b0, unsigned b1) {
    asm volatile("mma.sync.aligned.m16n8k16.row.col.f32.bf16.bf16.f32 "
        "{%0,%1,%2,%3}, {%4,%5,%6,%7}, {%8,%9}, {%0,%1,%2,%3};"
        : "+f"(d[0]), "+f"(d[1]), "+f"(d[2]), "+f"(d[3])
        : "r"(a[0]), "r"(a[1]), "r"(a[2]), "r"(a[3]), "r"(b0), "r"(b1));
}

__device__ __forceinline__ float sigf(float x) { return 1.0f / (1.0f + expf(-x)); }

// pack 8 fp32 -> 16B hi + 16B lo bf16 and store at (row, kb)
__device__ __forceinline__ void pack_store(char* smx, uint32_t offHi, uint32_t offLo,
                                           int row, int kb, const float* w8) {
    uint4 hi, lo;
    unsigned* hp = (unsigned*)&hi;
    unsigned* lp = (unsigned*)&lo;
#pragma unroll
    for (int q = 0; q < 4; q++) {
        float a = w8[2 * q], b = w8[2 * q + 1];
        __nv_bfloat16 ah = __float2bfloat16(a), bh = __float2bfloat16(b);
        __nv_bfloat16 al = __float2bfloat16(a - __bfloat162float(ah));
        __nv_bfloat16 bl = __float2bfloat16(b - __bfloat162float(bh));
        hp[q] = ((unsigned)__bfloat16_as_ushort(bh) << 16) | (unsigned)__bfloat16_as_ushort(ah);
        lp[q] = ((unsigned)__bfloat16_as_ushort(bl) << 16) | (unsigned)__bfloat16_as_ushort(al);
    }
    uint32_t a = toff(row, kb);
    *(uint4*)(smx + offHi + a) = hi;
    *(uint4*)(smx + offLo + a) = lo;
}

// stage 128x128 fp32 row-major matrix into hi/lo bf16 tiles — 256-thread version
__device__ __forceinline__ void stage_mat_256(const float* __restrict__ G, char* dst,
                                              uint32_t offHi, uint32_t offLo, int tid) {
    int row = tid >> 1, half = tid & 1;
    const float4* g4 = (const float4*)(G + (size_t)row * 128 + half * 64);
#pragma unroll
    for (int j = 0; j < 8; j++) {
        float4 qa = g4[2 * j], qb = g4[2 * j + 1];
        float w8[8] = { qa.x, qa.y, qa.z, qa.w, qb.x, qb.y, qb.z, qb.w };
        pack_store(dst, offHi, offLo, row, half * 8 + j, w8);
    }
}

// stage — 1024-thread version (each thread: 16 consecutive floats of one row)
__device__ __forceinline__ void stage_mat_1024(const float* __restrict__ G, char* dst,
                                               uint32_t offHi, uint32_t offLo, int tid) {
    int row = tid >> 3, q = tid & 7;
    const float4* g4 = (const float4*)(G + (size_t)row * 128 + q * 16);
#pragma unroll
    for (int j = 0; j < 2; j++) {
        float4 qa = g4[2 * j], qb = g4[2 * j + 1];
        float w8[8] = { qa.x, qa.y, qa.z, qa.w, qb.x, qb.y, qb.z, qb.w };
        pack_store(dst, offHi, offLo, row, q * 2 + j, w8);
    }
}

// cp.async the pre-built 64KB weight image for phase p into Ws (1024 threads)
__device__ __forceinline__ void cp_w(uint32_t sb, int p, int tid) {
    uint32_t sdst = sb + OFF_WHI + (uint32_t)tid * 16u;
    const char* gsrc = g_wt + (size_t)p * WSET_BYTES + (size_t)tid * 16u;
#pragma unroll
    for (int i = 0; i < 4; i++) {
        asm volatile("cp.async.cg.shared.global [%0], [%1], 16;"
            :: "r"(sdst + (uint32_t)i * 16384u), "l"(gsrc + (size_t)i * 16384u));
    }
    asm volatile("cp.async.commit_group;" ::: "memory");
}
#define CP_WAIT() asm volatile("cp.async.wait_group 0;" ::: "memory")

// store fp32 pair (cols c, c+1; c even) of row r into hi/lo tiles
__device__ __forceinline__ void st_pair(char* smx, uint32_t offHi, uint32_t offLo,
                                        int r, int c, float v0, float v1) {
    uint32_t a = toff(r, c >> 3) + (uint32_t)(c & 7) * 2u;
    __nv_bfloat16 h0 = __float2bfloat16(v0), h1 = __float2bfloat16(v1);
    __nv_bfloat16 l0 = __float2bfloat16(v0 - __bfloat162float(h0));
    __nv_bfloat16 l1 = __float2bfloat16(v1 - __bfloat162float(h1));
    *(unsigned*)(smx + offHi + a) =
        ((unsigned)__bfloat16_as_ushort(h1) << 16) | (unsigned)__bfloat16_as_ushort(h0);
    *(unsigned*)(smx + offLo + a) =
        ((unsigned)__bfloat16_as_ushort(l1) << 16) | (unsigned)__bfloat16_as_ushort(l0);
}

// read fp32 pair (hi+lo) at (r, c)
__device__ __forceinline__ float2 ld_pair(const char* smx, uint32_t offHi, uint32_t offLo,
                                          int r, int c) {
    uint32_t a = toff(r, c >> 3) + (uint32_t)(c & 7) * 2u;
    unsigned h = *(const unsigned*)(smx + offHi + a);
    unsigned l = *(const unsigned*)(smx + offLo + a);
    float2 v;
    v.x = __bfloat162float(__ushort_as_bfloat16((unsigned short)(h & 0xffff))) +
          __bfloat162float(__ushort_as_bfloat16((unsigned short)(l & 0xffff)));
    v.y = __bfloat162float(__ushort_as_bfloat16((unsigned short)(h >> 16))) +
          __bfloat162float(__ushort_as_bfloat16((unsigned short)(l >> 16)));
    return v;
}

// FUSED single-pass bf16x3-split GEMM, 32-warp variant: warp patch 16x32.
// acc += Ah·Wh + Ah·Wl + Al·Wh; each fragment loaded once per k-step.
__device__ __forceinline__ void gemm3(uint32_t sb, uint32_t offAhi, uint32_t offAlo,
                                      float acc[4][4], int m0, int n0, int lane) {
    const int rA  = m0 + (lane & 7) + ((lane >> 3) & 1) * 8;
    const int kA  = lane >> 4;            // A kb low bit
    const int rBb = (lane & 7) + (lane >> 4) * 8;
    const int kB  = (lane >> 3) & 1;      // B kb low bit
    const int swA = rA & 7;
    const uint32_t aH0 = sb + offAhi + (uint32_t)rA * 256u;
    const uint32_t aL0 = sb + offAlo + (uint32_t)rA * 256u;
#pragma unroll
    for (int s = 0; s < 8; s++) {
        int kb = 2 * s + kA;
        uint32_t ao = (uint32_t)((kb ^ swA) << 4);
        unsigned ah[4], al[4];
        ldm4(ah, aH0 + ao);
        ldm4(al, aL0 + ao);
        int kbB = 2 * s + kB;
#pragma unroll
        for (int q = 0; q < 2; q++) {
            int rB = n0 + q * 16 + rBb;
            uint32_t wo = (uint32_t)rB * 256u + (uint32_t)(((kbB ^ (rB & 7)) & 15) << 4);
            unsigned bh[4], bl[4];
            ldm4(bh, sb + OFF_WHI + wo);
            ldm4(bl, sb + OFF_WLO + wo);
            // Ah*Wh
            mma16816(acc[2 * q + 0], ah, bh[0], bh[1]);
            mma16816(acc[2 * q + 1], ah, bh[2], bh[3]);
            // Ah*Wl
            mma16816(acc[2 * q + 0], ah, bl[0], bl[1]);
            mma16816(acc[2 * q + 1], ah, bl[2], bl[3]);
            // Al*Wh
            mma16816(acc[2 * q + 0], al, bh[0], bh[1]);
            mma16816(acc[2 * q + 1], al, bh[2], bh[3]);
        }
    }
}

#define ZACC do {                                                         \
    _Pragma("unroll") for (int z2 = 0; z2 < 4; z2++)                      \
    _Pragma("unroll") for (int z3 = 0; z3 < 4; z3++) acc[z2][z3] = 0.f;   \
} while (0)

// ---------------- setup kernels ----------------

__global__ void k_winit() {
    int i = blockIdx.x * blockDim.x + threadIdx.x;
    if (i < NROWS) g_winner[i] = -1;
}
__global__ void k_wscatter(const int* __restrict__ idx) {
    int b = blockIdx.x * blockDim.x + threadIdx.x;
    if (b < BATCH) atomicMax(&g_winner[idx[b]], b);
}

// pre-convert the 8 weight matrices into swizzled bf16 hi/lo images
__global__ void k_wprep(const float* __restrict__ W1, const float* __restrict__ W2,
                        const float* __restrict__ W_ih, const float* __restrict__ W_hh) {
    const float* src;
    switch (blockIdx.x) {
        case 0: src = W1; break;
        case 1: src = W2; break;
        case 2: src = W_ih; break;                 // r, ih
        case 3: src = W_hh; break;                 // r, hh
        case 4: src = W_hh + 2 * 16384; break;     // n, hh
        case 5: src = W_ih + 2 * 16384; break;     // n, ih
        case 6: src = W_ih + 16384; break;         // z, ih
        default: src = W_hh + 16384; break;        // z, hh
    }
    char* dst = g_wt + (size_t)blockIdx.x * WSET_BYTES;
    stage_mat_256(src, dst, 0, TILE_BYTES, threadIdx.x);
}

// ---------------- tensor-core compute kernel (32 warps) ----------------

__global__ void __launch_bounds__(NTHREADS, 1) k_compute(
    const float* __restrict__ x, const int* __restrict__ idx,
    const float* __restrict__ hist,
    const float* __restrict__ b1, const float* __restrict__ b2,
    const float* __restrict__ b_ih, const float* __restrict__ b_hh,
    float* __restrict__ out, float* __restrict__ memout,
    float* __restrict__ nh)
{
    extern __shared__ char smx[];
    const uint32_t sb = smem_u32(smx);
    int* sIdx = (int*)(smx + OFF_IDX);

    const int tid  = threadIdx.x;
    const int wid  = tid >> 5, lane = tid & 31;
    const int m0   = (wid & 7) * 16;
    const int n0   = (wid >> 3) * 32;
    const int rBase = lane >> 2;
    const int cBase = (lane & 3) * 2;
    const long long rowbase = (long long)blockIdx.x * 128;

    // prefetch W for P1 while we stage X and M
    cp_w(sb, 0, tid);

    // ---- stage X ----
    stage_mat_1024(x + rowbase * Dm, smx, OFF_XHI, OFF_XLO, tid);

    // ---- gather + stage M (and write memout, cache idx) ----
    {
        int row = tid >> 3, q = tid & 7;
        int gi = idx[rowbase + row];
        if (q == 0) sIdx[row] = gi;
        const float4* g4 = (const float4*)(hist + (2LL * NROWS + gi) * Dm + q * 16);
        float4* mo = (float4*)(memout + (rowbase + row) * Dm + q * 16);
#pragma unroll
        for (int j = 0; j < 2; j++) {
            float4 qa = g4[2 * j], qb = g4[2 * j + 1];
            mo[2 * j] = qa; mo[2 * j + 1] = qb;
            float w8[8] = { qa.x, qa.y, qa.z, qa.w, qb.x, qb.y, qb.z, qb.w };
            pack_store(smx, OFF_MHI, OFF_MLO, row, q * 2 + j, w8);
        }
    }

    CP_WAIT();
    __syncthreads();

    float acc[4][4];
    float hold[4][4];

    // ===== P1: h1 = elu(x @ W1^T + b1) =====
    ZACC;
    gemm3(sb, OFF_XHI, OFF_XLO, acc, m0, n0, lane);
    __syncthreads();
    cp_w(sb, 1, tid);                               // W2, hidden under epilogue
#pragma unroll
    for (int nt = 0; nt < 4; nt++) {
        int c = n0 + nt * 8 + cBase;
        float2 bv = *(const float2*)(b1 + c);
#pragma unroll
        for (int eh = 0; eh < 2; eh++) {
            int r = m0 + rBase + eh * 8;
            float v0 = acc[nt][eh * 2 + 0] + bv.x;
            float v1 = acc[nt][eh * 2 + 1] + bv.y;
            v0 = (v0 > 0.f) ? v0 : expm1f(v0);
            v1 = (v1 > 0.f) ? v1 : expm1f(v1);
            st_pair(smx, OFF_XHI, OFF_XLO, r, c, v0, v1);
        }
    }
    CP_WAIT();
    __syncthreads();

    // ===== P2: xf = h1 @ W2^T + b2 =====
    ZACC;
    gemm3(sb, OFF_XHI, OFF_XLO, acc, m0, n0, lane);
    __syncthreads();
    cp_w(sb, 2, tid);                               // W_ih r
#pragma unroll
    for (int nt = 0; nt < 4; nt++) {
        int c = n0 + nt * 8 + cBase;
        float2 bv = *(const float2*)(b2 + c);
#pragma unroll
        for (int eh = 0; eh < 2; eh++) {
            int r = m0 + rBase + eh * 8;
            st_pair(smx, OFF_XHI, OFF_XLO, r, c,
                    acc[nt][eh * 2 + 0] + bv.x,
                    acc[nt][eh * 2 + 1] + bv.y);
        }
    }
    CP_WAIT();
    __syncthreads();

    // ===== P3: r = sigmoid(xf@Wihr^T + mem@Whhr^T + b_ihr + b_hhr) =====
    ZACC;
    gemm3(sb, OFF_XHI, OFF_XLO, acc, m0, n0, lane);
    __syncthreads();
    cp_w(sb, 3, tid);                               // W_hh r
    CP_WAIT();
    __syncthreads();
    gemm3(sb, OFF_MHI, OFF_MLO, acc, m0, n0, lane); // accumulate
    __syncthreads();
    cp_w(sb, 4, tid);                               // W_hh n
#pragma unroll
    for (int nt = 0; nt < 4; nt++) {
        int c = n0 + nt * 8 + cBase;
        float2 ba = *(const float2*)(b_ih + c);
        float2 bh = *(const float2*)(b_hh + c);
#pragma unroll
        for (int e = 0; e < 4; e++) {
            float bb = (e & 1) ? (ba.y + bh.y) : (ba.x + bh.x);
            hold[nt][e] = sigf(acc[nt][e] + bb);
        }
    }
    CP_WAIT();
    __syncthreads();

    // ===== P4: hold = r * (mem@Whhn^T + b_hhn) =====
    ZACC;
    gemm3(sb, OFF_MHI, OFF_MLO, acc, m0, n0, lane);
    __syncthreads();
    cp_w(sb, 5, tid);                               // W_ih n
#pragma unroll
    for (int nt = 0; nt < 4; nt++) {
        int c = n0 + nt * 8 + cBase;
        float2 bv = *(const float2*)(b_hh + 256 + c);
#pragma unroll
        for (int e = 0; e < 4; e++) {
            float bb = (e & 1) ? bv.y : bv.x;
            hold[nt][e] *= (acc[nt][e] + bb);
        }
    }
    CP_WAIT();
    __syncthreads();

    // ===== P5: hold = tanh(xf@Wihn^T + b_ihn + hold) =====
    ZACC;
    gemm3(sb, OFF_XHI, OFF_XLO, acc, m0, n0, lane);
    __syncthreads();
    cp_w(sb, 6, tid);                               // W_ih z
#pragma unroll
    for (int nt = 0; nt < 4; nt++) {
        int c = n0 + nt * 8 + cBase;
        float2 bv = *(const float2*)(b_ih + 256 + c);
#pragma unroll
        for (int e = 0; e < 4; e++) {
            float bb = (e & 1) ? bv.y : bv.x;
            hold[nt][e] = tanhf(acc[nt][e] + bb + hold[nt][e]);
        }
    }
    CP_WAIT();
    __syncthreads();

    // ===== P6: z gate + combine =====
    ZACC;
    gemm3(sb, OFF_XHI, OFF_XLO, acc, m0, n0, lane);
    __syncthreads();
    cp_w(sb, 7, tid);                               // W_hh z
    CP_WAIT();
    __syncthreads();
    gemm3(sb, OFF_MHI, OFF_MLO, acc, m0, n0, lane);
    // epilogue reads only M tiles (written before P1) — no sync needed
#pragma unroll
    for (int eh = 0; eh < 2; eh++) {
        int r = m0 + rBase + eh * 8;
        int grow = (int)rowbase + r;
        int gi = sIdx[r];
        bool win = (__ldg(&g_winner[gi]) == grow);
        float* orow = out + (long long)grow * Dm;
        float* hrow = nh + (2LL * NROWS + gi) * Dm;
#pragma unroll
        for (int nt = 0; nt < 4; nt++) {
            int c = n0 + nt * 8 + cBase;
            float2 ba = *(const float2*)(b_ih + 128 + c);
            float2 bh = *(const float2*)(b_hh + 128 + c);
            float2 mv = ld_pair(smx, OFF_MHI, OFF_MLO, r, c);
            float z0 = sigf(acc[nt][eh * 2 + 0] + ba.x + bh.x);
            float z1 = sigf(acc[nt][eh * 2 + 1] + ba.y + bh.y);
            float2 o;
            o.x = (1.f - z0) * hold[nt][eh * 2 + 0] + z0 * mv.x;
            o.y = (1.f - z1) * hold[nt][eh * 2 + 1] + z1 * mv.y;
            *(float2*)(orow + c) = o;
            if (win) *(float2*)(hrow + c) = o;
        }
    }
}

// ---------------- history copy (t=0,1 shift + t=2 non-winner) ----------------

__global__ void __maxnreg__(16) k_hist_copy(const float* __restrict__ hist,
                                            float* __restrict__ nh)
{
    const long long PER_T = (long long)NROWS * (Dm / 4);
    int t = blockIdx.y;
    long long rem = (long long)blockIdx.x * blockDim.x + threadIdx.x;
    int i = (int)(rem >> 5);
    int w = __ldg(&g_winner[i]);
    long long gid = (long long)t * PER_T + rem;
    if (t < TSLOTS - 1) {
        float4 v = __ldcs((const float4*)hist + gid + (w >= 0 ? PER_T : 0));
        __stcs((float4*)nh + gid, v);
    } else if (w < 0) {
        float4 v = __ldcs((const float4*)hist + gid);
        __stcs((float4*)nh + gid, v);
    }
}

// ---------------- launcher ----------------

extern "C" void kernel_launch(void* const* d_in, const int* in_sizes, int n_in,
                              void* d_out, int out_size) {
    (void)in_sizes; (void)n_in; (void)out_size;
    const float* x    = (const float*)d_in[0];
    const int*   idx  = (const int*)d_in[1];
    const float* hist = (const float*)d_in[2];
    const float* W1   = (const float*)d_in[3];
    const float* b1   = (const float*)d_in[4];
    const float* W2   = (const float*)d_in[5];
    const float* b2   = (const float*)d_in[6];
    const float* W_ih = (const float*)d_in[7];
    const float* b_ih = (const float*)d_in[8];
    const float* W_hh = (const float*)d_in[9];
    const float* b_hh = (const float*)d_in[10];

    float* out    = (float*)d_out;
    float* memout = out + (long long)BATCH * Dm;
    float* nh     = memout + (long long)BATCH * Dm;

    static cudaStream_t s2 = 0;
    static cudaEvent_t  eFork = 0, eJoin = 0;
    if (!s2) {
        cudaStreamCreateWithFlags(&s2, cudaStreamNonBlocking);
        cudaEventCreateWithFlags(&eFork, cudaEventDisableTiming);
        cudaEventCreateWithFlags(&eJoin, cudaEventDisableTiming);
        cudaFuncSetAttribute(k_compute, cudaFuncAttributeMaxDynamicSharedMemorySize,
                             SMEM_REQ);
    }

    k_winit<<<(NROWS + 511) / 512, 512>>>();
    k_wscatter<<<(BATCH + 255) / 256, 256>>>(idx);
    k_wprep<<<8, 256>>>(W1, W2, W_ih, W_hh);

    cudaEventRecord(eFork, 0);
    cudaStreamWaitEvent(s2, eFork, 0);

    k_compute<<<BATCH / 128, NTHREADS, SMEM_REQ>>>(x, idx, hist, b1, b2, b_ih, b_hh,
                                                   out, memout, nh);
    dim3 hg((unsigned)((long long)NROWS * (Dm / 4) / 128), TSLOTS);
    k_hist_copy<<<hg, 128, 0, s2>>>(hist, nh);

    cudaEventRecord(eJoin, s2);
    cudaStreamWaitEvent(0, eJoin, 0);
}

// round 15
// speedup vs baseline: 1.0207x; 1.0200x over previous
#include <cuda_runtime.h>
#include <cuda_bf16.h>
#include <math.h>
#include <stdint.h>

#define Dm      128
#define BATCH   65536
#define NROWS   500000
#define TSLOTS  3

#define TILE_BYTES 32768           // 128 rows x 256B (128 bf16)
#define OFF_XHI  0
#define OFF_XLO  (1 * TILE_BYTES)
#define OFF_MHI  (2 * TILE_BYTES)
#define OFF_MLO  (3 * TILE_BYTES)
#define OFF_WHI  (4 * TILE_BYTES)
#define OFF_WLO  (5 * TILE_BYTES)
#define OFF_IDX  (6 * TILE_BYTES)
#define SMEM_REQ (6 * TILE_BYTES + 512)

#define WSET_BYTES (2 * TILE_BYTES)   // hi+lo image of one matrix

#define NTHREADS 512

__device__ int g_winner[NROWS];
// pre-converted, pre-swizzled bf16 hi/lo smem images of the 8 weight matrices
__device__ __align__(1024) char g_wt[8 * WSET_BYTES];

// ---------------- low-level helpers ----------------

__device__ __forceinline__ uint32_t smem_u32(const void* p) {
    uint32_t a;
    asm("{ .reg .u64 t; cvta.to.shared.u64 t, %1; cvt.u32.u64 %0, t; }" : "=r"(a) : "l"(p));
    return a;
}

// swizzled byte offset of 16B chunk kb (0..15) in row r (0..127)
__device__ __forceinline__ uint32_t toff(int r, int kb) {
    return (uint32_t)r * 256u + (uint32_t)(((kb ^ (r & 7)) & 15) << 4);
}

__device__ __forceinline__ void ldm4(unsigned* d, uint32_t a) {
    asm volatile("ldmatrix.sync.aligned.m8n8.x4.shared.b16 {%0,%1,%2,%3}, [%4];"
        : "=r"(d[0]), "=r"(d[1]), "=r"(d[2]), "=r"(d[3]) : "r"(a));
}

__device__ __forceinline__ void mma16816(float* d, const unsigned* a,
                                         unsigned b0, unsigned b1) {
    asm volatile("mma.sync.aligned.m16n8k16.row.col.f32.bf16.bf16.f32 "
        "{%0,%1,%2,%3}, {%4,%5,%6,%7}, {%8,%9}, {%0,%1,%2,%3};"
        : "+f"(d[0]), "+f"(d[1]), "+f"(d[2]), "+f"(d[3])
        : "r"(a[0]), "r"(a[1]), "r"(a[2]), "r"(a[3]), "r"(b0), "r"(b1));
}

__device__ __forceinline__ float sigf(float x) {
    return 1.0f / (1.0f + __expf(-x));
}
__device__ __forceinline__ float tanhx(float x) {
    float r;
    asm("tanh.approx.f32 %0, %1;" : "=f"(r) : "f"(x));
    return r;
}

// pack 8 fp32 -> 16B hi + 16B lo bf16 and store at (row, kb)
__device__ __forceinline__ void pack_store(char* smx, uint32_t offHi, uint32_t offLo,
                                           int row, int kb, const float* w8) {
    uint4 hi, lo;
    unsigned* hp = (unsigned*)&hi;
    unsigned* lp = (unsigned*)&lo;
#pragma unroll
    for (int q = 0; q < 4; q++) {
        float a = w8[2 * q], b = w8[2 * q + 1];
        __nv_bfloat16 ah = __float2bfloat16(a), bh = __float2bfloat16(b);
        __nv_bfloat16 al = __float2bfloat16(a - __bfloat162float(ah));
        __nv_bfloat16 bl = __float2bfloat16(b - __bfloat162float(bh));
        hp[q] = ((unsigned)__bfloat16_as_ushort(bh) << 16) | (unsigned)__bfloat16_as_ushort(ah);
        lp[q] = ((unsigned)__bfloat16_as_ushort(bl) << 16) | (unsigned)__bfloat16_as_ushort(al);
    }
    uint32_t a = toff(row, kb);
    *(uint4*)(smx + offHi + a) = hi;
    *(uint4*)(smx + offLo + a) = lo;
}

// stage 128x128 fp32 row-major matrix into hi/lo bf16 tiles — 256-thread version
__device__ __forceinline__ void stage_mat_256(const float* __restrict__ G, char* dst,
                                              uint32_t offHi, uint32_t offLo, int tid) {
    int row = tid >> 1, half = tid & 1;
    const float4* g4 = (const float4*)(G + (size_t)row * 128 + half * 64);
#pragma unroll
    for (int j = 0; j < 8; j++) {
        float4 qa = g4[2 * j], qb = g4[2 * j + 1];
        float w8[8] = { qa.x, qa.y, qa.z, qa.w, qb.x, qb.y, qb.z, qb.w };
        pack_store(dst, offHi, offLo, row, half * 8 + j, w8);
    }
}

// stage — 512-thread version (each thread: 32 consecutive floats of one row)
__device__ __forceinline__ void stage_mat_512(const float* __restrict__ G, char* dst,
                                              uint32_t offHi, uint32_t offLo, int tid) {
    int row = tid >> 2, q = tid & 3;
    const float4* g4 = (const float4*)(G + (size_t)row * 128 + q * 32);
#pragma unroll
    for (int j = 0; j < 4; j++) {
        float4 qa = g4[2 * j], qb = g4[2 * j + 1];
        float w8[8] = { qa.x, qa.y, qa.z, qa.w, qb.x, qb.y, qb.z, qb.w };
        pack_store(dst, offHi, offLo, row, q * 4 + j, w8);
    }
}

// cp.async the pre-built 64KB weight image for phase p into Ws (512 threads)
__device__ __forceinline__ void cp_w(uint32_t sb, int p, int tid) {
    uint32_t sdst = sb + OFF_WHI + (uint32_t)tid * 16u;
    const char* gsrc = g_wt + (size_t)p * WSET_BYTES + (size_t)tid * 16u;
#pragma unroll
    for (int i = 0; i < 8; i++) {
        asm volatile("cp.async.cg.shared.global [%0], [%1], 16;"
            :: "r"(sdst + (uint32_t)i * 8192u), "l"(gsrc + (size_t)i * 8192u));
    }
    asm volatile("cp.async.commit_group;" ::: "memory");
}
#define CP_WAIT() asm volatile("cp.async.wait_group 0;" ::: "memory")

// store fp32 pair (cols c, c+1; c even) of row r into hi/lo tiles
__device__ __forceinline__ void st_pair(char* smx, uint32_t offHi, uint32_t offLo,
                                        int r, int c, float v0, float v1) {
    uint32_t a = toff(r, c >> 3) + (uint32_t)(c & 7) * 2u;
    __nv_bfloat16 h0 = __float2bfloat16(v0), h1 = __float2bfloat16(v1);
    __nv_bfloat16 l0 = __float2bfloat16(v0 - __bfloat162float(h0));
    __nv_bfloat16 l1 = __float2bfloat16(v1 - __bfloat162float(h1));
    *(unsigned*)(smx + offHi + a) =
        ((unsigned)__bfloat16_as_ushort(h1) << 16) | (unsigned)__bfloat16_as_ushort(h0);
    *(unsigned*)(smx + offLo + a) =
        ((unsigned)__bfloat16_as_ushort(l1) << 16) | (unsigned)__bfloat16_as_ushort(l0);
}

// read fp32 pair (hi+lo) at (r, c)
__device__ __forceinline__ float2 ld_pair(const char* smx, uint32_t offHi, uint32_t offLo,
                                          int r, int c) {
    uint32_t a = toff(r, c >> 3) + (uint32_t)(c & 7) * 2u;
    unsigned h = *(const unsigned*)(smx + offHi + a);
    unsigned l = *(const unsigned*)(smx + offLo + a);
    float2 v;
    v.x = __bfloat162float(__ushort_as_bfloat16((unsigned short)(h & 0xffff))) +
          __bfloat162float(__ushort_as_bfloat16((unsigned short)(l & 0xffff)));
    v.y = __bfloat162float(__ushort_as_bfloat16((unsigned short)(h >> 16))) +
          __bfloat162float(__ushort_as_bfloat16((unsigned short)(l >> 16)));
    return v;
}

// ---------------- software-pipelined fused bf16x3-split GEMM ----------------
// 16 warps, warp patch 32x32. Double-buffered k-loop: load step s+1's 8
// fragments while issuing step s's 24 MMAs. acc += Ah·Wh + Ah·Wl + Al·Wh.

__device__ __forceinline__ void gemm3(uint32_t sb, uint32_t offAhi, uint32_t offAlo,
                                      float acc[2][4][4], int m0, int n0, int lane) {
    const int rA  = m0 + (lane & 7) + ((lane >> 3) & 1) * 8;
    const int kA  = lane >> 4;            // A kb low bit
    const int rBb = (lane & 7) + (lane >> 4) * 8;
    const int kB  = (lane >> 3) & 1;      // B kb low bit
    const int swA = rA & 7;
    const uint32_t aH0 = sb + offAhi + (uint32_t)rA * 256u;
    const uint32_t aH1 = aH0 + 16u * 256u;
    const uint32_t aL0 = sb + offAlo + (uint32_t)rA * 256u;
    const uint32_t aL1 = aL0 + 16u * 256u;
    const int rB0 = n0 + rBb;
    const int rB1 = n0 + 16 + rBb;
    const uint32_t bH0 = sb + OFF_WHI + (uint32_t)rB0 * 256u;
    const uint32_t bL0 = sb + OFF_WLO + (uint32_t)rB0 * 256u;
    const uint32_t bH1 = sb + OFF_WHI + (uint32_t)rB1 * 256u;
    const uint32_t bL1 = sb + OFF_WLO + (uint32_t)rB1 * 256u;
    const int swB0 = rB0 & 7, swB1 = rB1 & 7;

    unsigned ah0[2][4], ah1[2][4], al0[2][4], al1[2][4];
    unsigned bh0[2][4], bl0[2][4], bh1[2][4], bl1[2][4];

#define LOADSTEP(s, buf) do {                                              \
        uint32_t ao  = (uint32_t)(((2 * (s) + kA) ^ swA) << 4);            \
        uint32_t bo0 = (uint32_t)((((2 * (s) + kB) ^ swB0) & 15) << 4);    \
        uint32_t bo1 = (uint32_t)((((2 * (s) + kB) ^ swB1) & 15) << 4);    \
        ldm4(ah0[buf], aH0 + ao);                                          \
        ldm4(ah1[buf], aH1 + ao);                                          \
        ldm4(al0[buf], aL0 + ao);                                          \
        ldm4(al1[buf], aL1 + ao);                                          \
        ldm4(bh0[buf], bH0 + bo0);                                         \
        ldm4(bl0[buf], bL0 + bo0);                                         \
        ldm4(bh1[buf], bH1 + bo1);                                         \
        ldm4(bl1[buf], bL1 + bo1);                                         \
    } while (0)

#define MMASTEP(buf) do {                                                  \
        mma16816(acc[0][0], ah0[buf], bh0[buf][0], bh0[buf][1]);           \
        mma16816(acc[0][1], ah0[buf], bh0[buf][2], bh0[buf][3]);           \
        mma16816(acc[1][0], ah1[buf], bh0[buf][0], bh0[buf][1]);           \
        mma16816(acc[1][1], ah1[buf], bh0[buf][2], bh0[buf][3]);           \
        mma16816(acc[0][2], ah0[buf], bh1[buf][0], bh1[buf][1]);           \
        mma16816(acc[0][3], ah0[buf], bh1[buf][2], bh1[buf][3]);           \
        mma16816(acc[1][2], ah1[buf], bh1[buf][0], bh1[buf][1]);           \
        mma16816(acc[1][3], ah1[buf], bh1[buf][2], bh1[buf][3]);           \
        mma16816(acc[0][0], ah0[buf], bl0[buf][0], bl0[buf][1]);           \
        mma16816(acc[0][1], ah0[buf], bl0[buf][2], bl0[buf][3]);           \
        mma16816(acc[1][0], ah1[buf], bl0[buf][0], bl0[buf][1]);           \
        mma16816(acc[1][1], ah1[buf], bl0[buf][2], bl0[buf][3]);           \
        mma16816(acc[0][2], ah0[buf], bl1[buf][0], bl1[buf][1]);           \
        mma16816(acc[0][3], ah0[buf], bl1[buf][2], bl1[buf][3]);           \
        mma16816(acc[1][2], ah1[buf], bl1[buf][0], bl1[buf][1]);           \
        mma16816(acc[1][3], ah1[buf], bl1[buf][2], bl1[buf][3]);           \
        mma16816(acc[0][0], al0[buf], bh0[buf][0], bh0[buf][1]);           \
        mma16816(acc[0][1], al0[buf], bh0[buf][2], bh0[buf][3]);           \
        mma16816(acc[1][0], al1[buf], bh0[buf][0], bh0[buf][1]);           \
        mma16816(acc[1][1], al1[buf], bh0[buf][2], bh0[buf][3]);           \
        mma16816(acc[0][2], al0[buf], bh1[buf][0], bh1[buf][1]);           \
        mma16816(acc[0][3], al0[buf], bh1[buf][2], bh1[buf][3]);           \
        mma16816(acc[1][2], al1[buf], bh1[buf][0], bh1[buf][1]);           \
        mma16816(acc[1][3], al1[buf], bh1[buf][2], bh1[buf][3]);           \
    } while (0)

    LOADSTEP(0, 0);
    LOADSTEP(1, 1);
    MMASTEP(0);
    LOADSTEP(2, 0);
    MMASTEP(1);
    LOADSTEP(3, 1);
    MMASTEP(0);
    LOADSTEP(4, 0);
    MMASTEP(1);
    LOADSTEP(5, 1);
    MMASTEP(0);
    LOADSTEP(6, 0);
    MMASTEP(1);
    LOADSTEP(7, 1);
    MMASTEP(0);
    MMASTEP(1);

#undef LOADSTEP
#undef MMASTEP
}

#define ZACC do {                                                         \
    _Pragma("unroll") for (int z1 = 0; z1 < 2; z1++)                      \
    _Pragma("unroll") for (int z2 = 0; z2 < 4; z2++)                      \
    _Pragma("unroll") for (int z3 = 0; z3 < 4; z3++) acc[z1][z2][z3] = 0.f; \
} while (0)

// ---------------- setup kernels ----------------

__global__ void k_winit() {
    int i = blockIdx.x * blockDim.x + threadIdx.x;
    if (i < NROWS) g_winner[i] = -1;
}
__global__ void k_wscatter(const int* __restrict__ idx) {
    int b = blockIdx.x * blockDim.x + threadIdx.x;
    if (b < BATCH) atomicMax(&g_winner[idx[b]], b);
}

// pre-convert the 8 weight matrices into swizzled bf16 hi/lo images
__global__ void k_wprep(const float* __restrict__ W1, const float* __restrict__ W2,
                        const float* __restrict__ W_ih, const float* __restrict__ W_hh) {
    const float* src;
    switch (blockIdx.x) {
        case 0: src = W1; break;
        case 1: src = W2; break;
        case 2: src = W_ih; break;                 // r, ih
        case 3: src = W_hh; break;                 // r, hh
        case 4: src = W_hh + 2 * 16384; break;     // n, hh
        case 5: src = W_ih + 2 * 16384; break;     // n, ih
        case 6: src = W_ih + 16384; break;         // z, ih
        default: src = W_hh + 16384; break;        // z, hh
    }
    char* dst = g_wt + (size_t)blockIdx.x * WSET_BYTES;
    stage_mat_256(src, dst, 0, TILE_BYTES, threadIdx.x);
}

// ---------------- tensor-core compute kernel (16 warps, pipelined) ----------------

__global__ void __maxnreg__(128) k_compute(
    const float* __restrict__ x, const int* __restrict__ idx,
    const float* __restrict__ hist,
    const float* __restrict__ b1, const float* __restrict__ b2,
    const float* __restrict__ b_ih, const float* __restrict__ b_hh,
    float* __restrict__ out, float* __restrict__ memout,
    float* __restrict__ nh)
{
    extern __shared__ char smx[];
    const uint32_t sb = smem_u32(smx);
    int* sIdx = (int*)(smx + OFF_IDX);

    const int tid  = threadIdx.x;
    const int wid  = tid >> 5, lane = tid & 31;
    const int m0   = (wid & 3) * 32;
    const int n0   = (wid >> 2) * 32;
    const int rBase = lane >> 2;
    const int cBase = (lane & 3) * 2;
    const long long rowbase = (long long)blockIdx.x * 128;

    // prefetch W for P1 while we stage X and M
    cp_w(sb, 0, tid);

    // ---- stage X ----
    stage_mat_512(x + rowbase * Dm, smx, OFF_XHI, OFF_XLO, tid);

    // ---- gather + stage M (and write memout, cache idx) ----
    {
        int row = tid >> 2, q = tid & 3;
        int gi = idx[rowbase + row];
        if (q == 0) sIdx[row] = gi;
        const float4* g4 = (const float4*)(hist + (2LL * NROWS + gi) * Dm + q * 32);
        float4* mo = (float4*)(memout + (rowbase + row) * Dm + q * 32);
#pragma unroll
        for (int j = 0; j < 4; j++) {
            float4 qa = g4[2 * j], qb = g4[2 * j + 1];
            mo[2 * j] = qa; mo[2 * j + 1] = qb;
            float w8[8] = { qa.x, qa.y, qa.z, qa.w, qb.x, qb.y, qb.z, qb.w };
            pack_store(smx, OFF_MHI, OFF_MLO, row, q * 4 + j, w8);
        }
    }

    CP_WAIT();
    __syncthreads();

    float acc[2][4][4];
    float hold[2][4][4];

    // ===== P1: h1 = elu(x @ W1^T + b1) =====
    ZACC;
    gemm3(sb, OFF_XHI, OFF_XLO, acc, m0, n0, lane);
    __syncthreads();
    cp_w(sb, 1, tid);                               // W2, hidden under epilogue
#pragma unroll
    for (int nt = 0; nt < 4; nt++) {
        int c = n0 + nt * 8 + cBase;
        float2 bv = *(const float2*)(b1 + c);
#pragma unroll
        for (int mt = 0; mt < 2; mt++)
#pragma unroll
            for (int eh = 0; eh < 2; eh++) {
                int r = m0 + mt * 16 + rBase + eh * 8;
                float v0 = acc[mt][nt][eh * 2 + 0] + bv.x;
                float v1 = acc[mt][nt][eh * 2 + 1] + bv.y;
                v0 = (v0 > 0.f) ? v0 : expm1f(v0);
                v1 = (v1 > 0.f) ? v1 : expm1f(v1);
                st_pair(smx, OFF_XHI, OFF_XLO, r, c, v0, v1);
            }
    }
    CP_WAIT();
    __syncthreads();

    // ===== P2: xf = h1 @ W2^T + b2 =====
    ZACC;
    gemm3(sb, OFF_XHI, OFF_XLO, acc, m0, n0, lane);
    __syncthreads();
    cp_w(sb, 2, tid);                               // W_ih r
#pragma unroll
    for (int nt = 0; nt < 4; nt++) {
        int c = n0 + nt * 8 + cBase;
        float2 bv = *(const float2*)(b2 + c);
#pragma unroll
        for (int mt = 0; mt < 2; mt++)
#pragma unroll
            for (int eh = 0; eh < 2; eh++) {
                int r = m0 + mt * 16 + rBase + eh * 8;
                st_pair(smx, OFF_XHI, OFF_XLO, r, c,
                        acc[mt][nt][eh * 2 + 0] + bv.x,
                        acc[mt][nt][eh * 2 + 1] + bv.y);
            }
    }
    CP_WAIT();
    __syncthreads();

    // ===== P3: r = sigmoid(xf@Wihr^T + mem@Whhr^T + b_ihr + b_hhr) =====
    ZACC;
    gemm3(sb, OFF_XHI, OFF_XLO, acc, m0, n0, lane);
    __syncthreads();
    cp_w(sb, 3, tid);                               // W_hh r
    CP_WAIT();
    __syncthreads();
    gemm3(sb, OFF_MHI, OFF_MLO, acc, m0, n0, lane); // accumulate
    __syncthreads();
    cp_w(sb, 4, tid);                               // W_hh n
#pragma unroll
    for (int nt = 0; nt < 4; nt++) {
        int c = n0 + nt * 8 + cBase;
        float2 ba = *(const float2*)(b_ih + c);
        float2 bh = *(const float2*)(b_hh + c);
#pragma unroll
        for (int mt = 0; mt < 2; mt++)
#pragma unroll
            for (int e = 0; e < 4; e++) {
                float bb = (e & 1) ? (ba.y + bh.y) : (ba.x + bh.x);
                hold[mt][nt][e] = sigf(acc[mt][nt][e] + bb);
            }
    }
    CP_WAIT();
    __syncthreads();

    // ===== P4: hold = r * (mem@Whhn^T + b_hhn) =====
    ZACC;
    gemm3(sb, OFF_MHI, OFF_MLO, acc, m0, n0, lane);
    __syncthreads();
    cp_w(sb, 5, tid);                               // W_ih n
#pragma unroll
    for (int nt = 0; nt < 4; nt++) {
        int c = n0 + nt * 8 + cBase;
        float2 bv = *(const float2*)(b_hh + 256 + c);
#pragma unroll
        for (int mt = 0; mt < 2; mt++)
#pragma unroll
            for (int e = 0; e < 4; e++) {
                float bb = (e & 1) ? bv.y : bv.x;
                hold[mt][nt][e] *= (acc[mt][nt][e] + bb);
            }
    }
    CP_WAIT();
    __syncthreads();

    // ===== P5: hold = tanh(xf@Wihn^T + b_ihn + hold) =====
    ZACC;
    gemm3(sb, OFF_XHI, OFF_XLO, acc, m0, n0, lane);
    __syncthreads();
    cp_w(sb, 6, tid);                               // W_ih z
#pragma unroll
    for (int nt = 0; nt < 4; nt++) {
        int c = n0 + nt * 8 + cBase;
        float2 bv = *(const float2*)(b_ih + 256 + c);
#pragma unroll
        for (int mt = 0; mt < 2; mt++)
#pragma unroll
            for (int e = 0; e < 4; e++) {
                float bb = (e & 1) ? bv.y : bv.x;
                hold[mt][nt][e] = tanhx(acc[mt][nt][e] + bb + hold[mt][nt][e]);
            }
    }
    CP_WAIT();
    __syncthreads();

    // ===== P6: z gate + combine =====
    ZACC;
    gemm3(sb, OFF_XHI, OFF_XLO, acc, m0, n0, lane);
    __syncthreads();
    cp_w(sb, 7, tid);                               // W_hh z
    CP_WAIT();
    __syncthreads();
    gemm3(sb, OFF_MHI, OFF_MLO, acc, m0, n0, lane);
    // epilogue reads only M tiles (written before P1) — no sync needed
#pragma unroll
    for (int mt = 0; mt < 2; mt++)
#pragma unroll
        for (int eh = 0; eh < 2; eh++) {
            int r = m0 + mt * 16 + rBase + eh * 8;
            int grow = (int)rowbase + r;
            int gi = sIdx[r];
            bool win = (__ldg(&g_winner[gi]) == grow);
            float* orow = out + (long long)grow * Dm;
            float* hrow = nh + (2LL * NROWS + gi) * Dm;
#pragma unroll
            for (int nt = 0; nt < 4; nt++) {
                int c = n0 + nt * 8 + cBase;
                float2 ba = *(const float2*)(b_ih + 128 + c);
                float2 bh = *(const float2*)(b_hh + 128 + c);
                float2 mv = ld_pair(smx, OFF_MHI, OFF_MLO, r, c);
                float z0 = sigf(acc[mt][nt][eh * 2 + 0] + ba.x + bh.x);
                float z1 = sigf(acc[mt][nt][eh * 2 + 1] + ba.y + bh.y);
                float2 o;
                o.x = (1.f - z0) * hold[mt][nt][eh * 2 + 0] + z0 * mv.x;
                o.y = (1.f - z1) * hold[mt][nt][eh * 2 + 1] + z1 * mv.y;
                *(float2*)(orow + c) = o;
                if (win) *(float2*)(hrow + c) = o;
            }
        }
}

// ---------------- history copy (t=0,1 shift + t=2 non-winner) ----------------

__global__ void __maxnreg__(16) k_hist_copy(const float* __restrict__ hist,
                                            float* __restrict__ nh)
{
    const long long PER_T = (long long)NROWS * (Dm / 4);
    int t = blockIdx.y;
    long long rem = (long long)blockIdx.x * blockDim.x + threadIdx.x;
    int i = (int)(rem >> 5);
    int w = __ldg(&g_winner[i]);
    long long gid = (long long)t * PER_T + rem;
    if (t < TSLOTS - 1) {
        float4 v = __ldcs((const float4*)hist + gid + (w >= 0 ? PER_T : 0));
        __stcs((float4*)nh + gid, v);
    } else if (w < 0) {
        float4 v = __ldcs((const float4*)hist + gid);
        __stcs((float4*)nh + gid, v);
    }
}

// ---------------- launcher ----------------

extern "C" void kernel_launch(void* const* d_in, const int* in_sizes, int n_in,
                              void* d_out, int out_size) {
    (void)in_sizes; (void)n_in; (void)out_size;
    const float* x    = (const float*)d_in[0];
    const int*   idx  = (const int*)d_in[1];
    const float* hist = (const float*)d_in[2];
    const float* W1   = (const float*)d_in[3];
    const float* b1   = (const float*)d_in[4];
    const float* W2   = (const float*)d_in[5];
    const float* b2   = (const float*)d_in[6];
    const float* W_ih = (const float*)d_in[7];
    const float* b_ih = (const float*)d_in[8];
    const float* W_hh = (const float*)d_in[9];
    const float* b_hh = (const float*)d_in[10];

    float* out    = (float*)d_out;
    float* memout = out + (long long)BATCH * Dm;
    float* nh     = memout + (long long)BATCH * Dm;

    static cudaStream_t s2 = 0;
    static cudaEvent_t  eFork = 0, eJoin = 0;
    if (!s2) {
        cudaStreamCreateWithFlags(&s2, cudaStreamNonBlocking);
        cudaEventCreateWithFlags(&eFork, cudaEventDisableTiming);
        cudaEventCreateWithFlags(&eJoin, cudaEventDisableTiming);
        cudaFuncSetAttribute(k_compute, cudaFuncAttributeMaxDynamicSharedMemorySize,
                             SMEM_REQ);
    }

    k_winit<<<(NROWS + 511) / 512, 512>>>();
    k_wscatter<<<(BATCH + 255) / 256, 256>>>(idx);
    k_wprep<<<8, 256>>>(W1, W2, W_ih, W_hh);

    cudaEventRecord(eFork, 0);
    cudaStreamWaitEvent(s2, eFork, 0);

    k_compute<<<BATCH / 128, NTHREADS, SMEM_REQ>>>(x, idx, hist, b1, b2, b_ih, b_hh,
                                                   out, memout, nh);
    dim3 hg((unsigned)((long long)NROWS * (Dm / 4) / 128), TSLOTS);
    k_hist_copy<<<hg, 128, 0, s2>>>(hist, nh);

    cudaEventRecord(eJoin, s2);
    cudaStreamWaitEvent(0, eJoin, 0);
}